// round 12
// baseline (speedup 1.0000x reference)
#include <cuda_runtime.h>
#include <cuda_fp16.h>
#include <cstdint>
#include <cstddef>

// ---------------------------------------------------------------------------
// 50-layer LSTM, persistent wavefront, fp16 m16n8k16 mma.sync.
//   B=64, T=256, D=H=256, L=50, O=2
//   R12: GPL=2, 100 CTAs (1/SM, balanced), 1024 threads / 32 warps,
//        warp tile 32x32 -> 8 warps per SMSP for latency hiding,
//        acc 32 regs, twin warps share B via L1, c-state in SMEM.
// ---------------------------------------------------------------------------

#define LAYERS 50
#define TSTEPS 256
#define GPL    2
#define NCTA   (LAYERS*GPL)                // 100 persistent CTAs, 1 per SM
#define HSLOT  16384                       // 64*256 halves per time slot
#define HLAYER ((size_t)(TSTEPS+1)*HSLOT)

#define SA_STRIDE 520                      // halves per SMEM A row
#define CB_STRIDE 136                      // floats per cbuf row
#define W_WARP_HALVES 16384                // per (l,gg,wn): 32kt*512 halves
#define SMEM_BYTES (64*SA_STRIDE*2 + 64*CB_STRIDE*4 + 512*4)   // 103424

__device__ __half   g_h16[(size_t)LAYERS*HLAYER];                 // ~421 MB
__device__ __half   g_w16[(size_t)LAYERS*2*16*W_WARP_HALVES];     // ~52 MB
__device__ float    g_bias[LAYERS*1024];
__device__ unsigned g_prog[128];

// ------------------------------- helpers -----------------------------------

__device__ __forceinline__ unsigned ld_acq(const unsigned* p) {
    unsigned v;
    asm volatile("ld.acquire.gpu.u32 %0, [%1];" : "=r"(v) : "l"(p) : "memory");
    return v;
}
__device__ __forceinline__ unsigned long long ld_acq64(const unsigned* p) {
    unsigned long long v;
    asm volatile("ld.acquire.gpu.u64 %0, [%1];" : "=l"(v) : "l"(p) : "memory");
    return v;
}
__device__ __forceinline__ void st_rel(unsigned* p, unsigned v) {
    asm volatile("st.release.gpu.u32 [%0], %1;" :: "l"(p), "r"(v) : "memory");
}
__device__ __forceinline__ void mma16(float* acc, const uint32_t a[4],
                                      uint32_t b0, uint32_t b1) {
    asm("mma.sync.aligned.m16n8k16.row.col.f32.f16.f16.f32 "
        "{%0,%1,%2,%3},{%4,%5,%6,%7},{%8,%9},{%0,%1,%2,%3};"
        : "+f"(acc[0]), "+f"(acc[1]), "+f"(acc[2]), "+f"(acc[3])
        : "r"(a[0]), "r"(a[1]), "r"(a[2]), "r"(a[3]), "r"(b0), "r"(b1));
}
__device__ __forceinline__ void ldsm4(uint32_t r[4], uint32_t saddr) {
    asm volatile("ldmatrix.sync.aligned.m8n8.x4.shared.b16 {%0,%1,%2,%3}, [%4];"
        : "=r"(r[0]), "=r"(r[1]), "=r"(r[2]), "=r"(r[3]) : "r"(saddr));
}
__device__ __forceinline__ float tanhfast(float x) {
    float y;
    asm("tanh.approx.f32 %0, %1;" : "=f"(y) : "f"(x));
    return y;
}
__device__ __forceinline__ float sigm(float x) {          // 1 MUFU
    return fmaf(tanhfast(0.5f * x), 0.5f, 0.5f);
}

// ------------------------------ prep kernels --------------------------------

// Pack weights into uint4-loadable fp16 B fragments, gate-blocked columns.
// half index: [l][gg(2)][wn(16)][kt(32)][j(2)][lane(32)][h(8)]
// Warp group wn owns units [8wn, 8wn+8); its 32 cols = gate(nt) x 8 units.
__global__ void prep_wfrag16(const float* __restrict__ Wih,
                             const float* __restrict__ Whh) {
    size_t idx = (size_t)blockIdx.x * 256 + threadIdx.x;
    int h    = (int)(idx & 7);
    int lane = (int)((idx >> 3)  & 31);
    int j    = (int)((idx >> 8)  & 1);
    int kt   = (int)((idx >> 9)  & 31);
    int wn   = (int)((idx >> 14) & 15);
    int gg   = (int)((idx >> 18) & 1);
    int l    = (int)(idx >> 19);
    if (l >= LAYERS) return;
    int jj = h >> 1, hb = h & 1;
    int nt  = j * 2 + (jj >> 1);             // gate 0..3 (i,f,g,o)
    int col = lane >> 2;                     // unit offset 0..7
    int k   = kt * 16 + (lane & 3) * 2 + hb + (jj & 1) * 8;
    int r = nt * 256 + gg * 128 + wn * 8 + col;
    float v = (k < 256) ? Wih[((size_t)l * 1024 + r) * 256 + k]
                        : Whh[((size_t)l * 1024 + r) * 256 + (k - 256)];
    g_w16[idx] = __float2half(v);
}

// sbias[l][gg][wn*32 + nt*8 + cc]
__global__ void prep_bias_init(const float* __restrict__ bih,
                               const float* __restrict__ bhh) {
    int idx = blockIdx.x * 256 + threadIdx.x;
    if (idx < LAYERS * 1024) {
        int l  = idx >> 10;
        int nl = idx & 1023;
        int gg = nl >> 9;
        int nn = nl & 511;
        int wn = nn >> 5;
        int nt = (nn >> 3) & 3;
        int cc = nn & 7;
        int r = nt * 256 + gg * 128 + wn * 8 + cc;
        g_bias[idx] = bih[l * 1024 + r] + bhh[l * 1024 + r];
    }
    if (idx < 128) g_prog[idx] = 0;
}

__global__ void zero_h0() {
    uint4* p = (uint4*)(g_h16 + (size_t)blockIdx.x * HLAYER);  // slot 0
    for (int i = threadIdx.x; i < 2048; i += 256)
        p[i] = make_uint4(0u, 0u, 0u, 0u);
}

// --------------------------- persistent LSTM --------------------------------

#define MMA_BLOCK(B0, B1)                                                     \
    _Pragma("unroll")                                                         \
    for (int mt = 0; mt < 2; ++mt) {                                          \
        mma16(acc[mt][0], av[mt], (B0).x, (B0).y);                            \
        mma16(acc[mt][1], av[mt], (B0).z, (B0).w);                            \
        mma16(acc[mt][2], av[mt], (B1).x, (B1).y);                            \
        mma16(acc[mt][3], av[mt], (B1).z, (B1).w);                            \
    }

__global__ void __launch_bounds__(1024, 1)
lstm_persistent(const float* __restrict__ x) {
    extern __shared__ char smem[];
    __half* sA    = (__half*)smem;                                 // 64*520
    float*  cbuf  = (float*)(smem + 64 * SA_STRIDE * 2);           // 64*136
    float*  sbias = (float*)(smem + 64 * SA_STRIDE * 2 + 64 * CB_STRIDE * 4);

    const int l    = blockIdx.x >> 1;
    const int gg   = blockIdx.x & 1;
    const int tid  = threadIdx.x;
    const int lane = tid & 31;
    const int w    = tid >> 5;      // 0..31
    const int wn   = w & 15;        // col group: units [8wn, 8wn+8)
    const int wm   = w >> 4;        // M half: rows [32wm, 32wm+32)
    const int q    = lane & 3;

    if (tid < 512) sbias[tid] = g_bias[(l * GPL + gg) * 512 + tid];
    for (int i = tid; i < 64 * CB_STRIDE; i += 1024) cbuf[i] = 0.f;
    // zero own h half in sA (h_{-1} = 0); peer half comes from global slot 0
    for (int i = tid; i < 1024; i += 1024) {
        int row = i >> 4, c8 = i & 15;
        *(uint4*)(sA + row * SA_STRIDE + 256 + gg * 128 + c8 * 8) =
            make_uint4(0u, 0u, 0u, 0u);
    }
    __syncthreads();

    const uint4* wv = (const uint4*)(g_w16 +
        (size_t)((l * GPL + gg) * 16 + wn) * W_WARP_HALVES);
    __half* hlayer = g_h16 + (size_t)l * HLAYER;
    const __half* hprev = (l > 0) ? (g_h16 + (size_t)(l - 1) * HLAYER) : nullptr;

    uint32_t sA_base = (uint32_t)__cvta_generic_to_shared(sA);
    const int rowA = wm * 32 + (lane & 15);   // base row for ldsm
    const int kofA = (lane >> 4) * 8;
    const int peer = gg ^ 1;

    float acc[2][4][4];        // [mt][gate][frag] : 32 regs

    for (int t = 0; t < TSTEPS; ++t) {
        // ---- wait: peer >= t (peer h half), prev layer >= t+1 (x ready) ----
        if (tid == 0) {
            if (t > 0) {
                while (ld_acq(&g_prog[l * GPL + peer]) < (unsigned)t)
                    __nanosleep(32);
            }
            if (l > 0) {
                const unsigned need = (unsigned)(t + 1);
                for (;;) {
                    unsigned long long v = ld_acq64(&g_prog[(l - 1) * GPL]);
                    if ((unsigned)v >= need && (unsigned)(v >> 32) >= need) break;
                    __nanosleep(32);
                }
            }
        }
        __syncthreads();

        // ---- stage x_t -> sA[0,256), peer h half -> sA[256+peer*128,+128) --
        if (l == 0) {
            #pragma unroll
            for (int i = tid; i < 4096; i += 1024) {      // 64 rows * 64 float4
                int row = i >> 6, c4 = i & 63;
                float4 v = __ldg((const float4*)(x +
                              ((size_t)row * TSTEPS + t) * 256) + c4);
                __half2* dst = (__half2*)(sA + row * SA_STRIDE + c4 * 4);
                dst[0] = __floats2half2_rn(v.x, v.y);
                dst[1] = __floats2half2_rn(v.z, v.w);
            }
        } else {
            const uint4* src = (const uint4*)(hprev + (size_t)(t + 1) * HSLOT);
            #pragma unroll
            for (int i = tid; i < 2048; i += 1024) {      // 64 rows * 32 uint4
                int row = i >> 5, c8 = i & 31;
                *(uint4*)(sA + row * SA_STRIDE + c8 * 8) = __ldg(src + i);
            }
        }
        {
            const __half* srcp = hlayer + (size_t)t * HSLOT + peer * 128;
            if (tid < 1024) {                             // 64 rows * 16 uint4
                int row = tid >> 4, c8 = tid & 15;
                *(uint4*)(sA + row * SA_STRIDE + 256 + peer * 128 + c8 * 8) =
                    __ldg((const uint4*)(srcp + (size_t)row * 256) + c8);
            }
        }

        // ---- init accumulators with bias ----
        #pragma unroll
        for (int nt = 0; nt < 4; ++nt) {
            float b0 = sbias[wn * 32 + nt * 8 + q * 2];
            float b1 = sbias[wn * 32 + nt * 8 + q * 2 + 1];
            #pragma unroll
            for (int mt = 0; mt < 2; ++mt) {
                acc[mt][nt][0] = b0; acc[mt][nt][1] = b1;
                acc[mt][nt][2] = b0; acc[mt][nt][3] = b1;
            }
        }
        __syncthreads();

        // ---- GEMM: gates += [x_t | h_{t-1}] @ Wc^T, depth-1 B prefetch ----
        {
            uint4 bbA = __ldg(wv + lane);
            uint4 bbB = __ldg(wv + 32 + lane);
            #pragma unroll 4
            for (int kt = 0; kt < 32; ++kt) {
                uint32_t av[2][4];
                #pragma unroll
                for (int mt = 0; mt < 2; ++mt) {
                    uint32_t addr = sA_base + (uint32_t)(
                        ((mt * 16 + rowA) * SA_STRIDE + kt * 16 + kofA) * 2);
                    ldsm4(av[mt], addr);
                }
                uint4 naA, naB;
                if (kt < 31) {
                    naA = __ldg(wv + (kt + 1) * 64 + lane);
                    naB = __ldg(wv + (kt + 1) * 64 + 32 + lane);
                }
                MMA_BLOCK(bbA, bbB)
                if (kt < 31) { bbA = naA; bbB = naB; }
            }
        }
        __syncthreads();   // all LDSM done before sA h-region is rewritten

        // ---- elementwise LSTM update (tanh.approx, c in SMEM) ----
        // element (mt,j): row = wm*32 + mt*16 + (lane>>2) + (j>>1)*8,
        // unit u0 = wn*8 + 2q + (j&1); gates acc[mt][0..3][j] = i,f,g,o
        __half* houtg = hlayer + (size_t)(t + 1) * HSLOT + gg * 128;
        __half* houts = sA + 256 + gg * 128;
        const int rbase = wm * 32 + (lane >> 2);
        const int u0 = wn * 8 + 2 * q;
        #pragma unroll
        for (int mt = 0; mt < 2; ++mt) {
            int row0 = mt * 16 + rbase;
            float2 c01 = *(float2*)&cbuf[row0 * CB_STRIDE + u0];
            float2 c23 = *(float2*)&cbuf[(row0 + 8) * CB_STRIDE + u0];
            float cv[4] = {c01.x, c01.y, c23.x, c23.y};
            float hv[4];
            #pragma unroll
            for (int j = 0; j < 4; ++j) {
                float i_ = sigm(acc[mt][0][j]);
                float f_ = sigm(acc[mt][1][j]);
                float g_ = tanhfast(acc[mt][2][j]);
                float o_ = sigm(acc[mt][3][j]);
                float cn = fmaf(f_, cv[j], i_ * g_);
                cv[j] = cn;
                hv[j] = o_ * tanhfast(cn);
            }
            *(float2*)&cbuf[row0 * CB_STRIDE + u0]       = make_float2(cv[0], cv[1]);
            *(float2*)&cbuf[(row0 + 8) * CB_STRIDE + u0] = make_float2(cv[2], cv[3]);
            __half2 h01 = __floats2half2_rn(hv[0], hv[1]);
            __half2 h23 = __floats2half2_rn(hv[2], hv[3]);
            *(__half2*)(houtg + (size_t)row0 * 256 + u0)       = h01;
            *(__half2*)(houtg + (size_t)(row0 + 8) * 256 + u0) = h23;
            *(__half2*)(houts + row0 * SA_STRIDE + u0)         = h01;
            *(__half2*)(houts + (row0 + 8) * SA_STRIDE + u0)   = h23;
        }

        __syncthreads();
        if (tid == 0) st_rel(&g_prog[l * GPL + gg], (unsigned)(t + 1));
    }
}

// ------------------------------ output head ---------------------------------

__global__ void out_proj(const float* __restrict__ Wout,
                         const float* __restrict__ bout,
                         float* __restrict__ out) {
    int p = blockIdx.x * 8 + (threadIdx.x >> 5);   // (t*64+b), 16384 total
    int lane = threadIdx.x & 31;
    int t = p >> 6, b = p & 63;
    const __half* h = g_h16 + (size_t)(LAYERS - 1) * HLAYER +
                      (size_t)(t + 1) * HSLOT + (size_t)b * 256 + lane * 8;
    uint4 hv = *(const uint4*)h;
    const __half2* hh = (const __half2*)&hv;
    const float* w0 = Wout + lane * 8;
    const float* w1 = Wout + 256 + lane * 8;
    float s0 = 0.f, s1 = 0.f;
    #pragma unroll
    for (int j = 0; j < 4; ++j) {
        float2 f = __half22float2(hh[j]);
        s0 += f.x * w0[2 * j] + f.y * w0[2 * j + 1];
        s1 += f.x * w1[2 * j] + f.y * w1[2 * j + 1];
    }
    #pragma unroll
    for (int off = 16; off > 0; off >>= 1) {
        s0 += __shfl_xor_sync(0xffffffffu, s0, off);
        s1 += __shfl_xor_sync(0xffffffffu, s1, off);
    }
    if (lane == 0) {
        float e0 = __expf(-(s0 + bout[0]));
        float e1 = __expf(-(s1 + bout[1]));
        out[(size_t)b * (TSTEPS * 2) + t * 2 + 0] = __fdividef(1.f, 1.f + e0);
        out[(size_t)b * (TSTEPS * 2) + t * 2 + 1] = __fdividef(1.f, 1.f + e1);
    }
}

// ------------------------------- launcher -----------------------------------

extern "C" void kernel_launch(void* const* d_in, const int* in_sizes, int n_in,
                              void* d_out, int out_size) {
    const float* x    = (const float*)d_in[0];
    const float* Wih  = (const float*)d_in[1];
    const float* Whh  = (const float*)d_in[2];
    const float* bih  = (const float*)d_in[3];
    const float* bhh  = (const float*)d_in[4];
    const float* Wout = (const float*)d_in[5];
    const float* bout = (const float*)d_in[6];
    float* out = (float*)d_out;

    cudaFuncSetAttribute(lstm_persistent,
                         cudaFuncAttributeMaxDynamicSharedMemorySize, SMEM_BYTES);

    prep_wfrag16<<<102400, 256>>>(Wih, Whh);    // 26.2M packed fp16 fragments
    prep_bias_init<<<200, 256>>>(bih, bhh);     // bias permute + progress reset
    zero_h0<<<LAYERS, 256>>>();                 // h_{-1} = 0 slots (fp16)
    lstm_persistent<<<NCTA, 1024, SMEM_BYTES>>>(x);
    out_proj<<<2048, 256>>>(Wout, bout, out);   // final sigmoid head
}